// round 11
// baseline (speedup 1.0000x reference)
#include <cuda_runtime.h>
#include <cstdint>

#define NQ     18
#define NREPS  3
#define NBATCH 64
#define IDIM   32

__device__ __forceinline__ float2 cmul(float2 a, float2 b) {
    return make_float2(a.x * b.x - a.y * b.y, a.x * b.y + a.y * b.x);
}
__device__ __forceinline__ float2 cmulc(float2 a, float2 b) {   // a * conj(b)
    return make_float2(a.x * b.x + a.y * b.y, a.y * b.x - a.x * b.y);
}
__device__ __forceinline__ float2 cadd(float2 a, float2 b) {
    return make_float2(a.x + b.x, a.y + b.y);
}
__device__ __forceinline__ float2 csub(float2 a, float2 b) {
    return make_float2(a.x - b.x, a.y - b.y);
}
__device__ __forceinline__ float2 shflx(float2 v, int m) {
    float2 r;
    r.x = __shfl_xor_sync(0xffffffffu, v.x, m);
    r.y = __shfl_xor_sync(0xffffffffu, v.y, m);
    return r;
}
// load 8 consecutive float2 (64B, 16B-aligned) as 4x LDS.128
__device__ __forceinline__ void ldrow8(const float2* p, float2* r) {
    const float4* q = (const float4*)p;
    float4 v0 = q[0], v1 = q[1], v2 = q[2], v3 = q[3];
    r[0] = make_float2(v0.x, v0.y); r[1] = make_float2(v0.z, v0.w);
    r[2] = make_float2(v1.x, v1.y); r[3] = make_float2(v1.z, v1.w);
    r[4] = make_float2(v2.x, v2.y); r[5] = make_float2(v2.z, v2.w);
    r[6] = make_float2(v3.x, v3.y); r[7] = make_float2(v3.z, v3.w);
}
// 4-accumulator complex dot: sum_m x[m]*y[m]
__device__ __forceinline__ float2 cdot8(const float2* x, const float2* y) {
    float2 a0 = cmul(x[0], y[0]);
    float2 a1 = cmul(x[1], y[1]);
    float2 a2 = cmul(x[2], y[2]);
    float2 a3 = cmul(x[3], y[3]);
    a0 = cadd(a0, cmul(x[4], y[4]));
    a1 = cadd(a1, cmul(x[5], y[5]));
    a2 = cadd(a2, cmul(x[6], y[6]));
    a3 = cadd(a3, cmul(x[7], y[7]));
    return cadd(cadd(a0, a1), cadd(a2, a3));
}
// 4-accumulator conj dot: sum_m x[m]*conj(y[m])
__device__ __forceinline__ float2 cdot8c(const float2* x, const float2* y) {
    float2 a0 = cmulc(x[0], y[0]);
    float2 a1 = cmulc(x[1], y[1]);
    float2 a2 = cmulc(x[2], y[2]);
    float2 a3 = cmulc(x[3], y[3]);
    a0 = cadd(a0, cmulc(x[4], y[4]));
    a1 = cadd(a1, cmulc(x[5], y[5]));
    a2 = cadd(a2, cmulc(x[6], y[6]));
    a3 = cadd(a3, cmulc(x[7], y[7]));
    return cadd(cadd(a0, a1), cadd(a2, a3));
}

#define CLUSTER_SYNC() do { \
    asm volatile("barrier.cluster.arrive.aligned;" ::: "memory"); \
    asm volatile("barrier.cluster.wait.aligned;"   ::: "memory"); \
} while (0)

__device__ __forceinline__ uint32_t smem_u32(const void* p) {
    uint32_t a;
    asm("{ .reg .u64 t; cvta.to.shared.u64 t, %1; cvt.u32.u64 %0, t; }"
        : "=r"(a) : "l"(p));
    return a;
}
// read 8 float2 from the peer CTA's shared memory (row base already mapa'd)
__device__ __forceinline__ void ldrow8_remote(uint32_t raddr, float2* r) {
    #pragma unroll
    for (int m = 0; m < 8; ++m) {
        float2 v;
        asm volatile("ld.shared::cluster.v2.f32 {%0,%1}, [%2];"
                     : "=f"(v.x), "=f"(v.y) : "r"(raddr + m * 8));
        r[m] = v;
    }
}

// Per-CTA smem layout (bytes). Each CTA keeps only ITS operator set:
//   [0,     23616)  MX : rank0 -> MH = M^dagger; rank1 -> M.  [9][4] blocks of
//                   82 f2, rows [8][10] (80B rows, conflict-free).
//   [23616, 46656)  G  (build) -> histories: rho(arr0)/sig(arr1)/D(arr2)/S(arr3),
//                   each [9][8][10] f2 (720 f2 apart). rank0 writes 0,2;
//                   rank1 writes 1,3. Epilogue reads 1,3 remotely via DSMEM.
//   [46656, 69696)  GT (build) -> tmp ([8] i-blocks of 36 f2)
#define SMEM_BYTES 69696

__global__ __launch_bounds__(256, 1) __cluster_dims__(2, 1, 1)
void qenc_kernel(
    const float* __restrict__ xin,   // (64, 32)
    const float* __restrict__ vp,    // (3, 18, 2)
    float* __restrict__ out)         // (64, 18)
{
    extern __shared__ __align__(16) char dyn[];
    float2* MXb  = (float2*)(dyn);
    float2* Gb   = (float2*)(dyn + 23616);
    float2* GTb  = (float2*)(dyn + 46656);
    float2* hist = (float2*)(dyn + 23616);
    float2* tmpb = (float2*)(dyn + 46656);

    __shared__ float sc[NQ][5][2];
    __shared__ float zred[NQ][8];

#define MXROW(pr,qq,r) (MXb + ((pr)*4+(qq))*82 + (r)*10)
#define GROW(k,z,r)    (Gb  + ((k)*2+(z))*80 + (r)*10)
#define GTROW(k,z,r)   (GTb + ((k)*2+(z))*80 + (r)*10)
#define HROW(arr,s,r)  (hist + (arr)*720 + (s)*80 + (r)*10)
#define HOFF(arr,s,r)  (23616u + ((arr)*720 + (s)*80 + (r)*10) * 8u)
#define HEL(arr,s,r,c) hist[(arr)*720 + (s)*80 + (r)*10 + (c)]
#define TMP(qq,ii)     (tmpb + (ii)*36 + (qq)*8)

    const int tid = threadIdx.x;
    uint32_t rank;
    asm("mov.u32 %0, %%cluster_ctarank;" : "=r"(rank));
    const int b = blockIdx.x >> 1;           // cluster = adjacent block pair

    // ---- setup: 5 sincos per site (RY(a)RY(b)=RY(a+b) collapses products) --
    if (tid < NQ * 5) {
        const int k = tid / 5;
        const int g = tid - k * 5;
        float th;
        if (g == 0)      th = vp[(0 * NQ + k) * 2 + 0];
        else if (g == 1) th = vp[(1 * NQ + k) * 2 + 0] + vp[(0 * NQ + k) * 2 + 1];
        else if (g == 2) th = vp[(2 * NQ + k) * 2 + 0] + vp[(1 * NQ + k) * 2 + 1];
        else if (g == 3) th = vp[(2 * NQ + k) * 2 + 1];
        else             th = xin[b * IDIM + k];
        float s, c;
        __sincosf(0.5f * th, &s, &c);
        sc[k][g][0] = c;
        sc[k][g][1] = s;
    }
    __syncthreads();

    // ---- build G[k][z][p][n] and its transpose (2304 entries, 9/thread) ----
    #pragma unroll
    for (int ii = 0; ii < 9; ++ii) {
        const int idx = tid + ii * 256;
        const int k = idx >> 7;
        const int z = (idx >> 6) & 1;
        const int p = (idx >> 3) & 7;
        const int n = idx & 7;
        const int n1 = n & 1, n2 = (n >> 1) & 1, n3 = (n >> 2) & 1;
        const int p1 = p & 1, p2 = (p >> 1) & 1, p3 = (p >> 2) & 1;
        const float r3  = (z == n3) ? sc[k][3][0] : (z == 0 ? -sc[k][3][1] : sc[k][3][1]);
        const int   i3  = n3 ^ p3;
        const float rc3 = (i3 == n2) ? sc[k][2][0] : (i3 == 0 ? -sc[k][2][1] : sc[k][2][1]);
        const int   i2  = n2 ^ p2;
        const float rc2 = (i2 == n1) ? sc[k][1][0] : (i2 == 0 ? -sc[k][1][1] : sc[k][1][1]);
        const float coef = r3 * rc3 * rc2;
        const float c1 = sc[k][0][0], s1 = sc[k][0][1];
        const float cx = sc[k][4][0], sx = sc[k][4][1];
        float2 w;
        if ((n1 ^ p1) == 0) w = make_float2(c1 * cx,  s1 * sx);
        else                w = make_float2(s1 * cx, -c1 * sx);
        const float2 val = make_float2(coef * w.x, coef * w.y);
        GROW(k, z, p)[n] = val;
        GTROW(k, z, n)[p] = val;
    }
    __syncthreads();

    // ---- build this CTA's operator set from M = G[2pr][z1] * G[2pr+1][z2] --
    // rank0 stores MH = M^dagger (left sweep); rank1 stores M (right sweep).
    #pragma unroll
    for (int ii = 0; ii < 9; ++ii) {
        const int idx = tid + ii * 256;
        const int pr = idx >> 8;
        const int qx = (idx >> 6) & 3;
        const int p  = (idx >> 3) & 7;
        const int n  = idx & 7;
        const int z1 = qx >> 1, z2 = qx & 1;
        float2 ra[8], rb[8];
        ldrow8(GROW(2 * pr, z1, p), ra);
        ldrow8(GTROW(2 * pr + 1, z2, n), rb);
        const float2 acc = cdot8(ra, rb);
        if (rank == 0) MXROW(pr, qx, n)[p] = make_float2(acc.x, -acc.y);  // MH
        else           MXROW(pr, qx, p)[n] = acc;                         // M
    }
    __syncthreads();   // G/GT dead; regions become histories / tmp

    // ---- lane roles: warp = owned row i; lane = (q, a) ----------------------
    const int i    = tid >> 5;          // 8 warps = 8 rows
    const int lane = tid & 31;
    const int q    = lane >> 3;
    const int a    = lane & 7;
    const int z2   = q & 1;
    const int z1   = q >> 1;

    // ---- step s = 0 (boundary envs trivial; single stage) -------------------
    {
        float2 t;
        if (rank == 0) {
            // rho^(0) = e0 e0^T: t_q[i][a] = M_q[0][i]*conj(M_q[0][a]) = MH[a][0]*conj? :
            t = cmulc(MXROW(0, q, a)[0], MXROW(0, q, i)[0]);
        } else {
            // sigma^(18) = J (closing vector of ones):
            // t_q[i][a] = rowsum(M_q,i) * conj(rowsum(M_q,a))
            float2 mi[8], ma[8];
            ldrow8(MXROW(8, q, i), mi);
            ldrow8(MXROW(8, q, a), ma);
            float2 ri = make_float2(0.f, 0.f), rj = make_float2(0.f, 0.f);
            #pragma unroll
            for (int m = 0; m < 8; ++m) { ri = cadd(ri, mi[m]); rj = cadd(rj, ma[m]); }
            t = cmulc(ri, rj);
        }
        const float2 u    = shflx(t, 8);
        const float2 sum2 = cadd(t, u);
        const float2 dif2 = z2 ? csub(u, t) : csub(t, u);      // t(z2=0)-t(z2=1)
        const float2 s2o  = shflx(sum2, 16);
        const float2 sum4 = cadd(sum2, s2o);
        const float2 d2o  = shflx(dif2, 16);
        const float2 difz2 = cadd(dif2, d2o);
        const float2 difz1 = z1 ? csub(s2o, sum2) : csub(sum2, s2o);
        if (rank == 0) {
            if (q == 0)      HEL(0, 1, i, a) = sum4;                            // rho^(2)
            else if (q == 1) HEL(2, 0, i, a) = difz2;                           // D[1]
            else if (q == 2) HEL(0, 0, i, a) = make_float2((i == 0 && a == 0) ? 1.f : 0.f, 0.f);
        } else {
            if (q == 0)      HEL(1, 1, i, a) = sum4;                            // sig^(16)
            else if (q == 1) HEL(3, 0, i, a) = difz1;                           // S[16]
            else if (q == 2) HEL(1, 0, i, a) = make_float2(1.f, 0.f);           // J
        }
    }
    __syncthreads();

    // ---- steps s = 1..8 (fully unrolled) ------------------------------------
    #pragma unroll
    for (int s = 1; s < 9; ++s) {
        float2 t;
        if (rank == 0) {
            // stage1: TMP[q][i][a] = conj( sum_m MH_q[i][m] * rho[a][m] )
            float2 r[8], mh[8];
            ldrow8(HROW(0, s, a), r);
            ldrow8(MXROW(s, q, i), mh);
            const float2 acc = cdot8(mh, r);
            TMP(q, i)[a] = make_float2(acc.x, -acc.y);
            __syncwarp();
            // stage2: t = sum_{a2} TMP[q][i][a2] * MH_q[a][a2]
            float2 tr[8], mr[8];
            ldrow8(TMP(q, i), tr);
            ldrow8(MXROW(s, q, a), mr);
            t = cdot8(tr, mr);
        } else {
            const int pr = 8 - s;
            // stage1: TMP[q][i][a] = sum_m M_q[i][m] * conj(sig[a][m])
            float2 r[8], mr[8];
            ldrow8(HROW(1, s, a), r);
            ldrow8(MXROW(pr, q, i), mr);
            TMP(q, i)[a] = cdot8c(mr, r);
            __syncwarp();
            // stage2: t = sum_{a2} TMP[q][i][a2] * conj(M_q[a][a2])
            float2 tr[8], ma[8];
            ldrow8(TMP(q, i), tr);
            ldrow8(MXROW(pr, q, a), ma);
            t = cdot8c(tr, ma);
        }
        const float2 u    = shflx(t, 8);
        const float2 sum2 = cadd(t, u);
        const float2 dif2 = z2 ? csub(u, t) : csub(t, u);
        const float2 s2o  = shflx(sum2, 16);
        const float2 sum4 = cadd(sum2, s2o);
        const float2 d2o  = shflx(dif2, 16);
        const float2 difz2 = cadd(dif2, d2o);
        const float2 difz1 = z1 ? csub(s2o, sum2) : csub(sum2, s2o);
        if (rank == 0) {
            if (q == 0)      { if (s < 8) HEL(0, s + 1, i, a) = sum4; }
            else if (q == 1) HEL(2, s, i, a) = difz2;                  // D[2s+1]
        } else {
            if (q == 0)      { if (s < 8) HEL(1, s + 1, i, a) = sum4; }
            else if (q == 1) HEL(3, s, i, a) = difz1;                  // S[16-2s]
        }
        __syncthreads();
    }

    // ---- join the cluster; rank0 computes all observables -------------------
    CLUSTER_SYNC();   // peer histories visible (arrive=release, wait=acquire)

    if (rank == 0) {
        // even t=2e: Re(rhoH[e] . S[8-e]);  odd t=2e+1: Re(Dh[e] . sig[8-e])
        if (tid < NQ * 8) {
            const int w = tid >> 3;
            const int r = tid & 7;
            const int e = w >> 1;
            float2 d[8], sm[8];
            uint32_t roff;
            if (w & 1) {
                ldrow8(HROW(2, e, r), d);                  // D (local)
                roff = HOFF(1, 8 - e, r);                  // sig (remote)
            } else {
                ldrow8(HROW(0, e, r), d);                  // rho (local)
                roff = HOFF(3, 8 - e, r);                  // S (remote)
            }
            uint32_t laddr = smem_u32(dyn) + roff;
            uint32_t raddr;
            asm("mapa.shared::cluster.u32 %0, %1, %2;" : "=r"(raddr) : "r"(laddr), "r"(1));
            ldrow8_remote(raddr, sm);
            float acc = 0.f;
            #pragma unroll
            for (int j = 0; j < 8; ++j)
                acc += d[j].x * sm[j].x - d[j].y * sm[j].y;
            zred[w][r] = acc;
        }
        __syncthreads();
        if (tid < NQ) {
            float sum = 0.f;
            #pragma unroll
            for (int j = 0; j < 8; ++j) sum += zred[tid][j];
            out[b * NQ + tid] = sum;
        }
    }

    CLUSTER_SYNC();   // keep peer smem alive until rank0 finished reading
}

extern "C" void kernel_launch(void* const* d_in, const int* in_sizes, int n_in,
                              void* d_out, int out_size)
{
    const float* x  = (const float*)d_in[0];   // input_vec (64,32)
    const float* vp = (const float*)d_in[1];   // var_params (3,18,2)
    if (n_in >= 2 && in_sizes[0] == NREPS * NQ * 2) {
        x  = (const float*)d_in[1];
        vp = (const float*)d_in[0];
    }
    cudaFuncSetAttribute(qenc_kernel,
                         cudaFuncAttributeMaxDynamicSharedMemorySize, SMEM_BYTES);
    qenc_kernel<<<NBATCH * 2, 256, SMEM_BYTES>>>(x, vp, (float*)d_out);
}

// round 12
// speedup vs baseline: 1.0153x; 1.0153x over previous
#include <cuda_runtime.h>

#define NQ     18
#define NREPS  3
#define NBATCH 64
#define IDIM   32

__device__ __forceinline__ float2 cmul(float2 a, float2 b) {
    return make_float2(a.x * b.x - a.y * b.y, a.x * b.y + a.y * b.x);
}
__device__ __forceinline__ float2 cmulc(float2 a, float2 b) {   // a * conj(b)
    return make_float2(a.x * b.x + a.y * b.y, a.y * b.x - a.x * b.y);
}
__device__ __forceinline__ float2 cadd(float2 a, float2 b) {
    return make_float2(a.x + b.x, a.y + b.y);
}
__device__ __forceinline__ float2 csub(float2 a, float2 b) {
    return make_float2(a.x - b.x, a.y - b.y);
}
__device__ __forceinline__ float2 shflx(float2 v, int m) {
    float2 r;
    r.x = __shfl_xor_sync(0xffffffffu, v.x, m);
    r.y = __shfl_xor_sync(0xffffffffu, v.y, m);
    return r;
}
__device__ __forceinline__ float2 shfl_idx(float2 v, int src) {
    float2 r;
    r.x = __shfl_sync(0xffffffffu, v.x, src);
    r.y = __shfl_sync(0xffffffffu, v.y, src);
    return r;
}
// load 8 consecutive float2 (64B, 16B-aligned) as 4x LDS.128
__device__ __forceinline__ void ldrow8(const float2* p, float2* r) {
    const float4* q = (const float4*)p;
    float4 v0 = q[0], v1 = q[1], v2 = q[2], v3 = q[3];
    r[0] = make_float2(v0.x, v0.y); r[1] = make_float2(v0.z, v0.w);
    r[2] = make_float2(v1.x, v1.y); r[3] = make_float2(v1.z, v1.w);
    r[4] = make_float2(v2.x, v2.y); r[5] = make_float2(v2.z, v2.w);
    r[6] = make_float2(v3.x, v3.y); r[7] = make_float2(v3.z, v3.w);
}
// 4-accumulator complex dot: sum_m x[m]*y[m]
__device__ __forceinline__ float2 cdot8(const float2* x, const float2* y) {
    float2 a0 = cmul(x[0], y[0]);
    float2 a1 = cmul(x[1], y[1]);
    float2 a2 = cmul(x[2], y[2]);
    float2 a3 = cmul(x[3], y[3]);
    a0 = cadd(a0, cmul(x[4], y[4]));
    a1 = cadd(a1, cmul(x[5], y[5]));
    a2 = cadd(a2, cmul(x[6], y[6]));
    a3 = cadd(a3, cmul(x[7], y[7]));
    return cadd(cadd(a0, a1), cadd(a2, a3));
}
// 4-accumulator conj dot: sum_m x[m]*conj(y[m])
__device__ __forceinline__ float2 cdot8c(const float2* x, const float2* y) {
    float2 a0 = cmulc(x[0], y[0]);
    float2 a1 = cmulc(x[1], y[1]);
    float2 a2 = cmulc(x[2], y[2]);
    float2 a3 = cmulc(x[3], y[3]);
    a0 = cadd(a0, cmulc(x[4], y[4]));
    a1 = cadd(a1, cmulc(x[5], y[5]));
    a2 = cadd(a2, cmulc(x[6], y[6]));
    a3 = cadd(a3, cmulc(x[7], y[7]));
    return cadd(cadd(a0, a1), cadd(a2, a3));
}

#define HALF_BAR(h) asm volatile("bar.sync %0, %1;" :: "r"(1 + (h)), "r"(256) : "memory")

// Matrix rows padded to 10 float2 (80B); (pr,q) blocks 82 f2. Layout (bytes):
//   [0,      23616)  M  [9][4] blocks of 82 f2, rows [8][10]   (right sweep)
//   [23616,  47232)  MH = M^dagger, same layout                (left sweep)
//   [47232,  70272)  G (build) -> histories rhoH/sigH/Dh/SH [9][8][10] f2 each
//   [70272,  93312)  GT (build only; dead after M build)
#define SMEM_BYTES 93312

__global__ __launch_bounds__(512, 1) void qenc_kernel(
    const float* __restrict__ xin,   // (64, 32)
    const float* __restrict__ vp,    // (3, 18, 2)
    float* __restrict__ out)         // (64, 18)
{
    extern __shared__ __align__(16) char dyn[];
    float2* Mb    = (float2*)(dyn);
    float2* MHb   = (float2*)(dyn + 23616);
    float2* Gb    = (float2*)(dyn + 47232);
    float2* GTb   = (float2*)(dyn + 70272);
    float2* hist  = (float2*)(dyn + 47232);

    __shared__ float sc[NQ][5][2];
    __shared__ float zred[NQ][8];

#define MROW(pr,qq,r)  (Mb  + ((pr)*4+(qq))*82 + (r)*10)
#define MHROW(pr,qq,r) (MHb + ((pr)*4+(qq))*82 + (r)*10)
#define GROW(k,z,r)    (Gb  + ((k)*2+(z))*80 + (r)*10)
#define GTROW(k,z,r)   (GTb + ((k)*2+(z))*80 + (r)*10)
#define HROW(arr,s,r)  (hist + (arr)*720 + (s)*80 + (r)*10)
#define HEL(arr,s,r,c) hist[(arr)*720 + (s)*80 + (r)*10 + (c)]

    const int b   = blockIdx.x;
    const int tid = threadIdx.x;

    // ---- setup: 5 sincos per site (RY(a)RY(b)=RY(a+b) collapses products) --
    if (tid < NQ * 5) {
        const int k = tid / 5;
        const int g = tid - k * 5;
        float th;
        if (g == 0)      th = vp[(0 * NQ + k) * 2 + 0];
        else if (g == 1) th = vp[(1 * NQ + k) * 2 + 0] + vp[(0 * NQ + k) * 2 + 1];
        else if (g == 2) th = vp[(2 * NQ + k) * 2 + 0] + vp[(1 * NQ + k) * 2 + 1];
        else if (g == 3) th = vp[(2 * NQ + k) * 2 + 1];
        else             th = xin[b * IDIM + k];
        float s, c;
        __sincosf(0.5f * th, &s, &c);
        sc[k][g][0] = c;
        sc[k][g][1] = s;
    }
    __syncthreads();

    // ---- build G[k][z][p][n] and its transpose ------------------------------
    #pragma unroll
    for (int ii = 0; ii < 5; ++ii) {
        const int idx = tid + ii * 512;
        if (idx < NQ * 128) {
            const int k = idx >> 7;
            const int z = (idx >> 6) & 1;
            const int p = (idx >> 3) & 7;
            const int n = idx & 7;
            const int n1 = n & 1, n2 = (n >> 1) & 1, n3 = (n >> 2) & 1;
            const int p1 = p & 1, p2 = (p >> 1) & 1, p3 = (p >> 2) & 1;
            const float r3  = (z == n3) ? sc[k][3][0] : (z == 0 ? -sc[k][3][1] : sc[k][3][1]);
            const int   i3  = n3 ^ p3;
            const float rc3 = (i3 == n2) ? sc[k][2][0] : (i3 == 0 ? -sc[k][2][1] : sc[k][2][1]);
            const int   i2  = n2 ^ p2;
            const float rc2 = (i2 == n1) ? sc[k][1][0] : (i2 == 0 ? -sc[k][1][1] : sc[k][1][1]);
            const float coef = r3 * rc3 * rc2;
            const float c1 = sc[k][0][0], s1 = sc[k][0][1];
            const float cx = sc[k][4][0], sx = sc[k][4][1];
            float2 w;
            if ((n1 ^ p1) == 0) w = make_float2(c1 * cx,  s1 * sx);
            else                w = make_float2(s1 * cx, -c1 * sx);
            const float2 val = make_float2(coef * w.x, coef * w.y);
            GROW(k, z, p)[n] = val;
            GTROW(k, z, n)[p] = val;
        }
    }
    __syncthreads();

    // ---- build M[pr][q] = G[2pr][z1]*G[2pr+1][z2], MH = M^dagger (1x2 tile) --
    #pragma unroll
    for (int ii = 0; ii < 3; ++ii) {
        const int idx = tid + ii * 512;
        if (idx < 9 * 4 * 8 * 4) {
            const int pr  = idx >> 7;
            const int rem = idx & 127;
            const int qx  = rem >> 5;
            const int p   = (rem >> 2) & 7;
            const int n0  = (rem & 3) * 2;
            const int z1 = qx >> 1, z2 = qx & 1;
            float2 ra[8], rb0[8], rb1[8];
            ldrow8(GROW(2 * pr, z1, p), ra);
            ldrow8(GTROW(2 * pr + 1, z2, n0), rb0);
            ldrow8(GTROW(2 * pr + 1, z2, n0 + 1), rb1);
            const float2 acc0 = cdot8(ra, rb0);
            const float2 acc1 = cdot8(ra, rb1);
            MROW(pr, qx, p)[n0]     = acc0;
            MROW(pr, qx, p)[n0 + 1] = acc1;
            MHROW(pr, qx, n0)[p]     = make_float2(acc0.x, -acc0.y);
            MHROW(pr, qx, n0 + 1)[p] = make_float2(acc1.x, -acc1.y);
        }
    }
    __syncthreads();   // G/GT dead; region becomes histories

    // ---- lane roles: warp = owned row i; lane = (q, a) ----------------------
    const int half = tid >> 8;          // 0 = left sweep, 1 = right sweep
    const int i    = (tid >> 5) & 7;    // warp-in-half = row
    const int lane = tid & 31;
    const int q    = lane >> 3;
    const int a    = lane & 7;
    const int z2   = q & 1;
    const int z1   = q >> 1;
    const int qb   = q * 8;

    // ---- step s = 0 (boundary envs trivial; single stage) -------------------
    {
        float2 t;
        if (half == 0) {
            // rho^(0) = e0 e0^T: t_q[i][a] = M_q[0][i] * conj(M_q[0][a])
            t = cmulc(MHROW(0, q, a)[0], MHROW(0, q, i)[0]);
        } else {
            // sigma^(18) = J: t_q[i][a] = rowsum(M_q,i) * conj(rowsum(M_q,a))
            float2 mi[8], ma[8];
            ldrow8(MROW(8, q, i), mi);
            ldrow8(MROW(8, q, a), ma);
            float2 ri = make_float2(0.f, 0.f), rj = make_float2(0.f, 0.f);
            #pragma unroll
            for (int m = 0; m < 8; ++m) { ri = cadd(ri, mi[m]); rj = cadd(rj, ma[m]); }
            t = cmulc(ri, rj);
        }
        const float2 u    = shflx(t, 8);
        const float2 sum2 = cadd(t, u);
        const float2 dif2 = z2 ? csub(u, t) : csub(t, u);      // t(z2=0)-t(z2=1)
        const float2 s2o  = shflx(sum2, 16);
        const float2 sum4 = cadd(sum2, s2o);
        const float2 d2o  = shflx(dif2, 16);
        const float2 difz2 = cadd(dif2, d2o);
        const float2 difz1 = z1 ? csub(s2o, sum2) : csub(sum2, s2o);
        if (half == 0) {
            if (q == 0)      HEL(0, 1, i, a) = sum4;                            // rho^(2)
            else if (q == 1) HEL(2, 0, i, a) = difz2;                           // D[1]
            else if (q == 2) HEL(0, 0, i, a) = make_float2((i == 0 && a == 0) ? 1.f : 0.f, 0.f);
        } else {
            if (q == 0)      HEL(1, 1, i, a) = sum4;                            // sig^(16)
            else if (q == 1) HEL(3, 0, i, a) = difz1;                           // S[16]
            else if (q == 2) HEL(1, 0, i, a) = make_float2(1.f, 0.f);           // J
        }
    }
    HALF_BAR(half);

    // ---- steps s = 1..8 (unrolled; shuffle-based stage2, no TMP smem) -------
    #pragma unroll
    for (int s = 1; s < 9; ++s) {
        float2 t;
        if (half == 0) {
            // stage1: tl = conj( sum_m MH_q[i][m] * rho[a][m] ) -> lane (q,a)
            float2 r[8], mh[8], mr[8];
            ldrow8(MHROW(s, q, a), mr);     // stage2 row, independent: hoisted
            ldrow8(HROW(0, s, a), r);
            ldrow8(MHROW(s, q, i), mh);
            const float2 acc = cdot8(mh, r);
            const float2 tl = make_float2(acc.x, -acc.y);
            // stage2: t[q][i][a] = sum_{a2} tl(lane q,a2) * MH_q[a][a2]
            float2 t0 = cmul(shfl_idx(tl, qb + 0), mr[0]);
            float2 t1 = cmul(shfl_idx(tl, qb + 1), mr[1]);
            float2 t2 = cmul(shfl_idx(tl, qb + 2), mr[2]);
            float2 t3 = cmul(shfl_idx(tl, qb + 3), mr[3]);
            t0 = cadd(t0, cmul(shfl_idx(tl, qb + 4), mr[4]));
            t1 = cadd(t1, cmul(shfl_idx(tl, qb + 5), mr[5]));
            t2 = cadd(t2, cmul(shfl_idx(tl, qb + 6), mr[6]));
            t3 = cadd(t3, cmul(shfl_idx(tl, qb + 7), mr[7]));
            t = cadd(cadd(t0, t1), cadd(t2, t3));
        } else {
            const int pr = 8 - s;
            // stage1: trr = sum_m M_q[i][m] * conj(sig[a][m]) -> lane (q,a)
            float2 r[8], mi[8], ma[8];
            ldrow8(MROW(pr, q, a), ma);     // stage2 row, hoisted
            ldrow8(HROW(1, s, a), r);
            ldrow8(MROW(pr, q, i), mi);
            const float2 trr = cdot8c(mi, r);
            // stage2: t[q][i][a] = sum_{a2} trr(lane q,a2) * conj(M_q[a][a2])
            float2 t0 = cmulc(shfl_idx(trr, qb + 0), ma[0]);
            float2 t1 = cmulc(shfl_idx(trr, qb + 1), ma[1]);
            float2 t2 = cmulc(shfl_idx(trr, qb + 2), ma[2]);
            float2 t3 = cmulc(shfl_idx(trr, qb + 3), ma[3]);
            t0 = cadd(t0, cmulc(shfl_idx(trr, qb + 4), ma[4]));
            t1 = cadd(t1, cmulc(shfl_idx(trr, qb + 5), ma[5]));
            t2 = cadd(t2, cmulc(shfl_idx(trr, qb + 6), ma[6]));
            t3 = cadd(t3, cmulc(shfl_idx(trr, qb + 7), ma[7]));
            t = cadd(cadd(t0, t1), cadd(t2, t3));
        }
        const float2 u    = shflx(t, 8);
        const float2 sum2 = cadd(t, u);
        const float2 dif2 = z2 ? csub(u, t) : csub(t, u);
        const float2 s2o  = shflx(sum2, 16);
        const float2 sum4 = cadd(sum2, s2o);
        const float2 d2o  = shflx(dif2, 16);
        const float2 difz2 = cadd(dif2, d2o);
        const float2 difz1 = z1 ? csub(s2o, sum2) : csub(sum2, s2o);
        if (half == 0) {
            if (q == 0)      { if (s < 8) HEL(0, s + 1, i, a) = sum4; }
            else if (q == 1) HEL(2, s, i, a) = difz2;                  // D[2s+1]
        } else {
            if (q == 0)      { if (s < 8) HEL(1, s + 1, i, a) = sum4; }
            else if (q == 1) HEL(3, s, i, a) = difz1;                  // S[16-2s]
        }
        HALF_BAR(half);
    }
    __syncthreads();   // join halves: epilogue reads both sides' histories

    // ---- observables --------------------------------------------------------
    // even t=2e: Re(rhoH[e] . SH[8-e]);  odd t=2e+1: Re(Dh[e] . sigH[8-e])
    if (tid < NQ * 8) {
        const int w = tid >> 3;
        const int r = tid & 7;
        const int e = w >> 1;
        const float2* dmat = (w & 1) ? HROW(2, e, r)     : HROW(0, e, r);
        const float2* smat = (w & 1) ? HROW(1, 8 - e, r) : HROW(3, 8 - e, r);
        float2 d[8], sm[8];
        ldrow8(dmat, d);
        ldrow8(smat, sm);
        float acc = 0.f;
        #pragma unroll
        for (int j = 0; j < 8; ++j)
            acc += d[j].x * sm[j].x - d[j].y * sm[j].y;
        zred[w][r] = acc;
    }
    __syncthreads();
    if (tid < NQ) {
        float sum = 0.f;
        #pragma unroll
        for (int j = 0; j < 8; ++j) sum += zred[tid][j];
        out[b * NQ + tid] = sum;
    }
}

extern "C" void kernel_launch(void* const* d_in, const int* in_sizes, int n_in,
                              void* d_out, int out_size)
{
    const float* x  = (const float*)d_in[0];   // input_vec (64,32)
    const float* vp = (const float*)d_in[1];   // var_params (3,18,2)
    if (n_in >= 2 && in_sizes[0] == NREPS * NQ * 2) {
        x  = (const float*)d_in[1];
        vp = (const float*)d_in[0];
    }
    cudaFuncSetAttribute(qenc_kernel,
                         cudaFuncAttributeMaxDynamicSharedMemorySize, SMEM_BYTES);
    qenc_kernel<<<NBATCH, 512, SMEM_BYTES>>>(x, vp, (float*)d_out);
}

// round 13
// speedup vs baseline: 1.1181x; 1.1012x over previous
#include <cuda_runtime.h>
#include <cstring>

#define NQ     18
#define NREPS  3
#define NBATCH 64
#define IDIM   32

__device__ __forceinline__ float2 cmul(float2 a, float2 b) {
    return make_float2(a.x * b.x - a.y * b.y, a.x * b.y + a.y * b.x);
}
__device__ __forceinline__ float2 cmulc(float2 a, float2 b) {   // a * conj(b)
    return make_float2(a.x * b.x + a.y * b.y, a.y * b.x - a.x * b.y);
}
// packed f32x2 add (sm_100a): one instruction for a complex add
__device__ __forceinline__ float2 cadd(float2 a, float2 b) {
    unsigned long long ua, ub, uo;
    memcpy(&ua, &a, 8); memcpy(&ub, &b, 8);
    asm("add.rn.f32x2 %0, %1, %2;" : "=l"(uo) : "l"(ua), "l"(ub));
    float2 o; memcpy(&o, &uo, 8);
    return o;
}
__device__ __forceinline__ float2 csub(float2 a, float2 b) {
    return make_float2(a.x - b.x, a.y - b.y);
}
__device__ __forceinline__ float2 shflx(float2 v, int m) {
    float2 r;
    r.x = __shfl_xor_sync(0xffffffffu, v.x, m);
    r.y = __shfl_xor_sync(0xffffffffu, v.y, m);
    return r;
}
// load 8 consecutive float2 (64B, 16B-aligned) as 4x LDS.128
__device__ __forceinline__ void ldrow8(const float2* p, float2* r) {
    const float4* q = (const float4*)p;
    float4 v0 = q[0], v1 = q[1], v2 = q[2], v3 = q[3];
    r[0] = make_float2(v0.x, v0.y); r[1] = make_float2(v0.z, v0.w);
    r[2] = make_float2(v1.x, v1.y); r[3] = make_float2(v1.z, v1.w);
    r[4] = make_float2(v2.x, v2.y); r[5] = make_float2(v2.z, v2.w);
    r[6] = make_float2(v3.x, v3.y); r[7] = make_float2(v3.z, v3.w);
}
// 4-accumulator complex dot: sum_m x[m]*y[m]
__device__ __forceinline__ float2 cdot8(const float2* x, const float2* y) {
    float2 a0 = cmul(x[0], y[0]);
    float2 a1 = cmul(x[1], y[1]);
    float2 a2 = cmul(x[2], y[2]);
    float2 a3 = cmul(x[3], y[3]);
    a0 = cadd(a0, cmul(x[4], y[4]));
    a1 = cadd(a1, cmul(x[5], y[5]));
    a2 = cadd(a2, cmul(x[6], y[6]));
    a3 = cadd(a3, cmul(x[7], y[7]));
    return cadd(cadd(a0, a1), cadd(a2, a3));
}
// 4-accumulator conj dot: sum_m x[m]*conj(y[m])
__device__ __forceinline__ float2 cdot8c(const float2* x, const float2* y) {
    float2 a0 = cmulc(x[0], y[0]);
    float2 a1 = cmulc(x[1], y[1]);
    float2 a2 = cmulc(x[2], y[2]);
    float2 a3 = cmulc(x[3], y[3]);
    a0 = cadd(a0, cmulc(x[4], y[4]));
    a1 = cadd(a1, cmulc(x[5], y[5]));
    a2 = cadd(a2, cmulc(x[6], y[6]));
    a3 = cadd(a3, cmulc(x[7], y[7]));
    return cadd(cadd(a0, a1), cadd(a2, a3));
}

#define HALF_BAR(h) asm volatile("bar.sync %0, %1;" :: "r"(1 + (h)), "r"(256) : "memory")

// Matrix rows padded to 10 float2 (80B); (pr,q) blocks 82 f2. Layout (bytes):
//   [0,      23616)  M  [9][4] blocks of 82 f2, rows [8][10]   (right sweep)
//   [23616,  47232)  MH = M^dagger, same layout                (left sweep)
//   [47232,  70272)  G (build) -> histories rhoH/sigH/Dh/SH [9][8][10] f2 each
//   [70272,  93312)  GT (build) -> tmpL [8]x36 f2, tmpR after
#define SMEM_BYTES 93312

__global__ __launch_bounds__(512, 1) void qenc_kernel(
    const float* __restrict__ xin,   // (64, 32)
    const float* __restrict__ vp,    // (3, 18, 2)
    float* __restrict__ out)         // (64, 18)
{
    extern __shared__ __align__(16) char dyn[];
    float2* Mb    = (float2*)(dyn);
    float2* MHb   = (float2*)(dyn + 23616);
    float2* Gb    = (float2*)(dyn + 47232);
    float2* GTb   = (float2*)(dyn + 70272);
    float2* hist  = (float2*)(dyn + 47232);
    float2* tmpLb = (float2*)(dyn + 70272);
    float2* tmpRb = (float2*)(dyn + 70272 + 288 * 8);

    __shared__ float sc[NQ][5][2];
    __shared__ float zred[NQ][8];

#define MROW(pr,qq,r)  (Mb  + ((pr)*4+(qq))*82 + (r)*10)
#define MHROW(pr,qq,r) (MHb + ((pr)*4+(qq))*82 + (r)*10)
#define GROW(k,z,r)    (Gb  + ((k)*2+(z))*80 + (r)*10)
#define GTROW(k,z,r)   (GTb + ((k)*2+(z))*80 + (r)*10)
#define HROW(arr,s,r)  (hist + (arr)*720 + (s)*80 + (r)*10)
#define HEL(arr,s,r,c) hist[(arr)*720 + (s)*80 + (r)*10 + (c)]
#define TL(qq,ii)      (tmpLb + (ii)*36 + (qq)*8)
#define TR(qq,ii)      (tmpRb + (ii)*36 + (qq)*8)

    const int b   = blockIdx.x;
    const int tid = threadIdx.x;

    // ---- setup: 5 sincos per site (RY(a)RY(b)=RY(a+b) collapses products) --
    if (tid < NQ * 5) {
        const int k = tid / 5;
        const int g = tid - k * 5;
        float th;
        if (g == 0)      th = vp[(0 * NQ + k) * 2 + 0];
        else if (g == 1) th = vp[(1 * NQ + k) * 2 + 0] + vp[(0 * NQ + k) * 2 + 1];
        else if (g == 2) th = vp[(2 * NQ + k) * 2 + 0] + vp[(1 * NQ + k) * 2 + 1];
        else if (g == 3) th = vp[(2 * NQ + k) * 2 + 1];
        else             th = xin[b * IDIM + k];
        float s, c;
        __sincosf(0.5f * th, &s, &c);
        sc[k][g][0] = c;
        sc[k][g][1] = s;
    }
    __syncthreads();

    // ---- build G[k][z][p][n] and its transpose ------------------------------
    #pragma unroll
    for (int ii = 0; ii < 5; ++ii) {
        const int idx = tid + ii * 512;
        if (idx < NQ * 128) {
            const int k = idx >> 7;
            const int z = (idx >> 6) & 1;
            const int p = (idx >> 3) & 7;
            const int n = idx & 7;
            const int n1 = n & 1, n2 = (n >> 1) & 1, n3 = (n >> 2) & 1;
            const int p1 = p & 1, p2 = (p >> 1) & 1, p3 = (p >> 2) & 1;
            const float r3  = (z == n3) ? sc[k][3][0] : (z == 0 ? -sc[k][3][1] : sc[k][3][1]);
            const int   i3  = n3 ^ p3;
            const float rc3 = (i3 == n2) ? sc[k][2][0] : (i3 == 0 ? -sc[k][2][1] : sc[k][2][1]);
            const int   i2  = n2 ^ p2;
            const float rc2 = (i2 == n1) ? sc[k][1][0] : (i2 == 0 ? -sc[k][1][1] : sc[k][1][1]);
            const float coef = r3 * rc3 * rc2;
            const float c1 = sc[k][0][0], s1 = sc[k][0][1];
            const float cx = sc[k][4][0], sx = sc[k][4][1];
            float2 w;
            if ((n1 ^ p1) == 0) w = make_float2(c1 * cx,  s1 * sx);
            else                w = make_float2(s1 * cx, -c1 * sx);
            const float2 val = make_float2(coef * w.x, coef * w.y);
            GROW(k, z, p)[n] = val;
            GTROW(k, z, n)[p] = val;
        }
    }
    __syncthreads();

    // ---- build M[pr][q] = G[2pr][z1]*G[2pr+1][z2], MH = M^dagger (1x2 tile) --
    #pragma unroll
    for (int ii = 0; ii < 3; ++ii) {
        const int idx = tid + ii * 512;
        if (idx < 9 * 4 * 8 * 4) {
            const int pr  = idx >> 7;
            const int rem = idx & 127;
            const int qx  = rem >> 5;
            const int p   = (rem >> 2) & 7;
            const int n0  = (rem & 3) * 2;
            const int z1 = qx >> 1, z2 = qx & 1;
            float2 ra[8], rb0[8], rb1[8];
            ldrow8(GROW(2 * pr, z1, p), ra);
            ldrow8(GTROW(2 * pr + 1, z2, n0), rb0);
            ldrow8(GTROW(2 * pr + 1, z2, n0 + 1), rb1);
            const float2 acc0 = cdot8(ra, rb0);
            const float2 acc1 = cdot8(ra, rb1);
            MROW(pr, qx, p)[n0]     = acc0;
            MROW(pr, qx, p)[n0 + 1] = acc1;
            MHROW(pr, qx, n0)[p]     = make_float2(acc0.x, -acc0.y);
            MHROW(pr, qx, n0 + 1)[p] = make_float2(acc1.x, -acc1.y);
        }
    }
    __syncthreads();   // G/GT dead; regions become histories / tmp

    // ---- lane roles: warp = owned row i; lane = (q, a) ----------------------
    const int half = tid >> 8;          // 0 = left sweep, 1 = right sweep
    const int i    = (tid >> 5) & 7;    // warp-in-half = row
    const int lane = tid & 31;
    const int q    = lane >> 3;
    const int a    = lane & 7;
    const int z2   = q & 1;
    const int z1   = q >> 1;

    // ---- step s = 0 (boundary envs trivial; single stage) -------------------
    {
        float2 t;
        if (half == 0) {
            // rho^(0) = e0 e0^T: t_q[i][a] = M_q[0][i] * conj(M_q[0][a])
            t = cmulc(MHROW(0, q, a)[0], MHROW(0, q, i)[0]);
        } else {
            // sigma^(18) = J: t_q[i][a] = rowsum(M_q,i) * conj(rowsum(M_q,a))
            float2 mi[8], ma[8];
            ldrow8(MROW(8, q, i), mi);
            ldrow8(MROW(8, q, a), ma);
            float2 ri = make_float2(0.f, 0.f), rj = make_float2(0.f, 0.f);
            #pragma unroll
            for (int m = 0; m < 8; ++m) { ri = cadd(ri, mi[m]); rj = cadd(rj, ma[m]); }
            t = cmulc(ri, rj);
        }
        const float2 u    = shflx(t, 8);
        const float2 sum2 = cadd(t, u);
        const float2 dif2 = z2 ? csub(u, t) : csub(t, u);      // t(z2=0)-t(z2=1)
        const float2 s2o  = shflx(sum2, 16);
        const float2 sum4 = cadd(sum2, s2o);
        const float2 d2o  = shflx(dif2, 16);
        const float2 difz2 = cadd(dif2, d2o);
        const float2 difz1 = z1 ? csub(s2o, sum2) : csub(sum2, s2o);
        if (half == 0) {
            if (q == 0)      HEL(0, 1, i, a) = sum4;                            // rho^(2)
            else if (q == 1) HEL(2, 0, i, a) = difz2;                           // D[1]
            else if (q == 2) HEL(0, 0, i, a) = make_float2((i == 0 && a == 0) ? 1.f : 0.f, 0.f);
        } else {
            if (q == 0)      HEL(1, 1, i, a) = sum4;                            // sig^(16)
            else if (q == 1) HEL(3, 0, i, a) = difz1;                           // S[16]
            else if (q == 2) HEL(1, 0, i, a) = make_float2(1.f, 0.f);           // J
        }
    }
    HALF_BAR(half);

    // ---- steps s = 1..8 (fully unrolled; per-half named barriers) -----------
    #pragma unroll
    for (int s = 1; s < 9; ++s) {
        float2 t;
        if (half == 0) {
            // stage1: TL[q][i][a] = conj( sum_m MH_q[i][m] * rho[a][m] )
            float2 r[8], mh[8];
            ldrow8(HROW(0, s, a), r);
            ldrow8(MHROW(s, q, i), mh);
            const float2 acc = cdot8(mh, r);
            TL(q, i)[a] = make_float2(acc.x, -acc.y);
            __syncwarp();
            // stage2: t = sum_{a2} TL[q][i][a2] * MH_q[a][a2]
            float2 tr[8], mr[8];
            ldrow8(TL(q, i), tr);
            ldrow8(MHROW(s, q, a), mr);
            t = cdot8(tr, mr);
        } else {
            const int pr = 8 - s;
            // stage1: TR[q][i][a] = sum_m M_q[i][m] * conj(sig[a][m])
            float2 r[8], mr[8];
            ldrow8(HROW(1, s, a), r);
            ldrow8(MROW(pr, q, i), mr);
            TR(q, i)[a] = cdot8c(mr, r);
            __syncwarp();
            // stage2: t = sum_{a2} TR[q][i][a2] * conj(M_q[a][a2])
            float2 tr[8], ma[8];
            ldrow8(TR(q, i), tr);
            ldrow8(MROW(pr, q, a), ma);
            t = cdot8c(tr, ma);
        }
        const float2 u    = shflx(t, 8);
        const float2 sum2 = cadd(t, u);
        const float2 dif2 = z2 ? csub(u, t) : csub(t, u);
        const float2 s2o  = shflx(sum2, 16);
        const float2 sum4 = cadd(sum2, s2o);
        const float2 d2o  = shflx(dif2, 16);
        const float2 difz2 = cadd(dif2, d2o);
        const float2 difz1 = z1 ? csub(s2o, sum2) : csub(sum2, s2o);
        if (half == 0) {
            if (q == 0)      { if (s < 8) HEL(0, s + 1, i, a) = sum4; }
            else if (q == 1) HEL(2, s, i, a) = difz2;                  // D[2s+1]
        } else {
            if (q == 0)      { if (s < 8) HEL(1, s + 1, i, a) = sum4; }
            else if (q == 1) HEL(3, s, i, a) = difz1;                  // S[16-2s]
        }
        if (s < 8) HALF_BAR(half);   // last step is ordered by the join below
    }
    __syncthreads();   // join halves: epilogue reads both sides' histories

    // ---- observables --------------------------------------------------------
    // even t=2e: Re(rhoH[e] . SH[8-e]);  odd t=2e+1: Re(Dh[e] . sigH[8-e])
    if (tid < NQ * 8) {
        const int w = tid >> 3;
        const int r = tid & 7;
        const int e = w >> 1;
        const float2* dmat = (w & 1) ? HROW(2, e, r)     : HROW(0, e, r);
        const float2* smat = (w & 1) ? HROW(1, 8 - e, r) : HROW(3, 8 - e, r);
        float2 d[8], sm[8];
        ldrow8(dmat, d);
        ldrow8(smat, sm);
        float acc = 0.f;
        #pragma unroll
        for (int j = 0; j < 8; ++j)
            acc += d[j].x * sm[j].x - d[j].y * sm[j].y;
        zred[w][r] = acc;
    }
    __syncthreads();
    if (tid < NQ) {
        float sum = 0.f;
        #pragma unroll
        for (int j = 0; j < 8; ++j) sum += zred[tid][j];
        out[b * NQ + tid] = sum;
    }
}

extern "C" void kernel_launch(void* const* d_in, const int* in_sizes, int n_in,
                              void* d_out, int out_size)
{
    const float* x  = (const float*)d_in[0];   // input_vec (64,32)
    const float* vp = (const float*)d_in[1];   // var_params (3,18,2)
    if (n_in >= 2 && in_sizes[0] == NREPS * NQ * 2) {
        x  = (const float*)d_in[1];
        vp = (const float*)d_in[0];
    }
    cudaFuncSetAttribute(qenc_kernel,
                         cudaFuncAttributeMaxDynamicSharedMemorySize, SMEM_BYTES);
    qenc_kernel<<<NBATCH, 512, SMEM_BYTES>>>(x, vp, (float*)d_out);
}